// round 1
// baseline (speedup 1.0000x reference)
#include <cuda_runtime.h>
#include <cstdint>

#define LEN_T 13294
#define B_T 2
#define M_TOT (B_T * LEN_T)   // 26588
#define D_T 256
#define NH_T 8
#define DH_T 32
#define DFF_T 1024

// ---------------- scratch (static device globals; no allocation) ----------------
__device__ float g_query[(size_t)M_TOT * D_T];
__device__ float g_value[(size_t)M_TOT * D_T];
__device__ float g_off  [(size_t)M_TOT * D_T];
__device__ float g_attw [(size_t)M_TOT * 128];
__device__ float g_attn [(size_t)M_TOT * D_T];
__device__ float g_x1   [(size_t)M_TOT * D_T];
__device__ float g_hid  [(size_t)M_TOT * DFF_T];

// ---------------- elementwise add: query = src + pos ----------------
__global__ void add_vec(const float* __restrict__ a, const float* __restrict__ b,
                        float* __restrict__ o, int n4) {
    int i = blockIdx.x * blockDim.x + threadIdx.x;
    if (i >= n4) return;
    float4 x = ((const float4*)a)[i];
    float4 y = ((const float4*)b)[i];
    ((float4*)o)[i] = make_float4(x.x + y.x, x.y + y.y, x.z + y.z, x.w + y.w);
}

// ---------------- SGEMM: C[M,N] = A[M,K] @ B[K,N] + bias (+relu / +res) ----------------
// Tile: 128(M) x 64(N), BK=16, 256 threads, 8x4 per thread. N % 64 == 0, K % 16 == 0.
// EPI: 0 = bias, 1 = bias+relu, 2 = bias+residual
template <int EPI>
__global__ void __launch_bounds__(256)
sgemm(const float* __restrict__ A, const float* __restrict__ Bm,
      const float* __restrict__ bias, const float* __restrict__ res,
      float* __restrict__ C, int M, int N, int K)
{
    __shared__ float As[16][128];
    __shared__ float Bs[16][64];

    const int bm = blockIdx.y * 128;
    const int bn = blockIdx.x * 64;
    const int tid = threadIdx.x;
    const int tx = tid & 15;   // col group: 4 cols
    const int ty = tid >> 4;   // row group: 8 rows

    float acc[8][4];
#pragma unroll
    for (int i = 0; i < 8; i++)
#pragma unroll
        for (int j = 0; j < 4; j++) acc[i][j] = 0.f;

    for (int k0 = 0; k0 < K; k0 += 16) {
        // load A tile 128x16 (512 float4, 2 per thread), store transposed
#pragma unroll
        for (int i = 0; i < 2; i++) {
            int idx  = tid + i * 256;
            int row  = idx >> 2;       // 0..127
            int colv = idx & 3;        // float4 index within 16 cols
            int grow = bm + row;
            float4 v = make_float4(0.f, 0.f, 0.f, 0.f);
            if (grow < M)
                v = *(const float4*)(A + (size_t)grow * K + k0 + colv * 4);
            As[colv * 4 + 0][row] = v.x;
            As[colv * 4 + 1][row] = v.y;
            As[colv * 4 + 2][row] = v.z;
            As[colv * 4 + 3][row] = v.w;
        }
        // load B tile 16x64 (256 float4, 1 per thread)
        {
            int row  = tid >> 4;   // 0..15
            int colv = tid & 15;   // 16 float4 per row
            float4 v = *(const float4*)(Bm + (size_t)(k0 + row) * N + bn + colv * 4);
            *(float4*)&Bs[row][colv * 4] = v;
        }
        __syncthreads();

#pragma unroll
        for (int k = 0; k < 16; k++) {
            float4 a0 = *(const float4*)&As[k][ty * 8];
            float4 a1 = *(const float4*)&As[k][ty * 8 + 4];
            float4 bv = *(const float4*)&Bs[k][tx * 4];
            float a[8] = {a0.x, a0.y, a0.z, a0.w, a1.x, a1.y, a1.z, a1.w};
            float bb[4] = {bv.x, bv.y, bv.z, bv.w};
#pragma unroll
            for (int i = 0; i < 8; i++)
#pragma unroll
                for (int j = 0; j < 4; j++) acc[i][j] = fmaf(a[i], bb[j], acc[i][j]);
        }
        __syncthreads();
    }

    float4 bvv = *(const float4*)(bias + bn + tx * 4);
    float bvals[4] = {bvv.x, bvv.y, bvv.z, bvv.w};
#pragma unroll
    for (int i = 0; i < 8; i++) {
        int grow = bm + ty * 8 + i;
        if (grow < M) {
            float o[4];
#pragma unroll
            for (int j = 0; j < 4; j++) o[j] = acc[i][j] + bvals[j];
            if (EPI == 1) {
#pragma unroll
                for (int j = 0; j < 4; j++) o[j] = fmaxf(o[j], 0.f);
            }
            if (EPI == 2) {
                float4 r = *(const float4*)(res + (size_t)grow * N + bn + tx * 4);
                o[0] += r.x; o[1] += r.y; o[2] += r.z; o[3] += r.w;
            }
            *(float4*)(C + (size_t)grow * N + bn + tx * 4) =
                make_float4(o[0], o[1], o[2], o[3]);
        }
    }
}

// ---------------- softmax over 16 (per b,l,h) in place ----------------
__global__ void softmax16(float* __restrict__ a) {
    int r = blockIdx.x * blockDim.x + threadIdx.x;
    if (r >= M_TOT * NH_T) return;
    float* p = a + (size_t)r * 16;
    float v[16], mx = -1e30f;
#pragma unroll
    for (int i = 0; i < 16; i++) { v[i] = p[i]; mx = fmaxf(mx, v[i]); }
    float s = 0.f;
#pragma unroll
    for (int i = 0; i < 16; i++) { v[i] = __expf(v[i] - mx); s += v[i]; }
    float inv = 1.f / s;
#pragma unroll
    for (int i = 0; i < 16; i++) p[i] = v[i] * inv;
}

// ---------------- deformable sampling: warp per (b,l,h), lane = channel ----------------
__global__ void __launch_bounds__(256)
deform_sample(const float* __restrict__ value, const float* __restrict__ off,
              const float* __restrict__ attw, const float* __restrict__ ref,
              float* __restrict__ out)
{
    const int cH[4] = {100, 50, 25, 13};
    const int cW[4] = {100, 50, 25, 13};
    const int cS[4] = {0, 10000, 12500, 13125};

    int t = blockIdx.x * blockDim.x + threadIdx.x;
    int warp = t >> 5, lane = t & 31;
    if (warp >= M_TOT * NH_T) return;
    int h = warp & 7;
    int m = warp >> 3;          // b*LEN + l
    int b = m / LEN_T;

    const float* offp = off  + (size_t)m * 256 + h * 32;   // [NL][NP][2]
    const float* awp  = attw + (size_t)warp * 16;          // [NL][NP]
    const float* refp = ref  + (size_t)m * 8;              // [NL][2]
    const float* vb   = value + (size_t)b * LEN_T * 256 + h * 32 + lane;

    float acc = 0.f;
#pragma unroll
    for (int lvl = 0; lvl < 4; lvl++) {
        const int H = cH[lvl], W = cW[lvl];
        const float* vl = vb + (size_t)cS[lvl] * 256;
        float rx = refp[lvl * 2], ry = refp[lvl * 2 + 1];
        float bx = rx * (float)W - 0.5f;
        float by = ry * (float)H - 0.5f;
#pragma unroll
        for (int p = 0; p < 4; p++) {
            float x = bx + offp[(lvl * 4 + p) * 2];
            float y = by + offp[(lvl * 4 + p) * 2 + 1];
            float aw = awp[lvl * 4 + p];
            float xf = floorf(x), yf = floorf(y);
            float dx = x - xf, dy = y - yf;
            int x0 = (int)xf, y0 = (int)yf;
            float w00 = (1.f - dx) * (1.f - dy) * aw;
            float w10 = dx * (1.f - dy) * aw;
            float w01 = (1.f - dx) * dy * aw;
            float w11 = dx * dy * aw;
            bool ix0 = (unsigned)x0 < (unsigned)W;
            bool ix1 = (unsigned)(x0 + 1) < (unsigned)W;
            bool iy0 = (unsigned)y0 < (unsigned)H;
            bool iy1 = (unsigned)(y0 + 1) < (unsigned)H;
            if (ix0 && iy0) acc += w00 * vl[(size_t)(y0 * W + x0) * 256];
            if (ix1 && iy0) acc += w10 * vl[(size_t)(y0 * W + x0 + 1) * 256];
            if (ix0 && iy1) acc += w01 * vl[(size_t)((y0 + 1) * W + x0) * 256];
            if (ix1 && iy1) acc += w11 * vl[(size_t)((y0 + 1) * W + x0 + 1) * 256];
        }
    }
    out[(size_t)warp * 32 + lane] = acc;
}

// ---------------- layernorm: warp per row of 256 ----------------
__global__ void ln_warp(const float* __restrict__ x, const float* __restrict__ g,
                        const float* __restrict__ b, float* __restrict__ o)
{
    int t = blockIdx.x * blockDim.x + threadIdx.x;
    int warp = t >> 5, lane = t & 31;
    if (warp >= M_TOT) return;
    const float4* row = (const float4*)(x + (size_t)warp * 256);
    float4 v0 = row[lane];
    float4 v1 = row[lane + 32];
    float s = v0.x + v0.y + v0.z + v0.w + v1.x + v1.y + v1.z + v1.w;
#pragma unroll
    for (int off = 16; off; off >>= 1) s += __shfl_xor_sync(0xffffffffu, s, off);
    float mean = s * (1.f / 256.f);
    float d[8] = {v0.x - mean, v0.y - mean, v0.z - mean, v0.w - mean,
                  v1.x - mean, v1.y - mean, v1.z - mean, v1.w - mean};
    float ss = 0.f;
#pragma unroll
    for (int i = 0; i < 8; i++) ss += d[i] * d[i];
#pragma unroll
    for (int off = 16; off; off >>= 1) ss += __shfl_xor_sync(0xffffffffu, ss, off);
    float rs = rsqrtf(ss * (1.f / 256.f) + 1e-5f);
    const float4* g4 = (const float4*)g;
    const float4* b4 = (const float4*)b;
    float4 G0 = g4[lane], G1 = g4[lane + 32];
    float4 B0 = b4[lane], B1 = b4[lane + 32];
    float4 o0 = make_float4(d[0] * rs * G0.x + B0.x, d[1] * rs * G0.y + B0.y,
                            d[2] * rs * G0.z + B0.z, d[3] * rs * G0.w + B0.w);
    float4 o1 = make_float4(d[4] * rs * G1.x + B1.x, d[5] * rs * G1.y + B1.y,
                            d[6] * rs * G1.z + B1.z, d[7] * rs * G1.w + B1.w);
    float4* orow = (float4*)(o + (size_t)warp * 256);
    orow[lane] = o0;
    orow[lane + 32] = o1;
}

// ---------------- launch ----------------
extern "C" void kernel_launch(void* const* d_in, const int* in_sizes, int n_in,
                              void* d_out, int out_size)
{
    const float* src   = (const float*)d_in[0];
    const float* pos   = (const float*)d_in[1];
    const float* ref   = (const float*)d_in[2];
    const float* Wv    = (const float*)d_in[3];
    const float* bv    = (const float*)d_in[4];
    const float* Woff  = (const float*)d_in[5];
    const float* boff  = (const float*)d_in[6];
    const float* Wattn = (const float*)d_in[7];
    const float* battn = (const float*)d_in[8];
    const float* Wout  = (const float*)d_in[9];
    const float* bout  = (const float*)d_in[10];
    const float* W1    = (const float*)d_in[11];
    const float* b1    = (const float*)d_in[12];
    const float* W2    = (const float*)d_in[13];
    const float* b2    = (const float*)d_in[14];
    const float* gm1   = (const float*)d_in[15];
    const float* be1   = (const float*)d_in[16];
    const float* gm2   = (const float*)d_in[17];
    const float* be2   = (const float*)d_in[18];
    float* out = (float*)d_out;

    float *q, *v, *off, *aw, *at, *x1, *hid;
    cudaGetSymbolAddress((void**)&q,   g_query);
    cudaGetSymbolAddress((void**)&v,   g_value);
    cudaGetSymbolAddress((void**)&off, g_off);
    cudaGetSymbolAddress((void**)&aw,  g_attw);
    cudaGetSymbolAddress((void**)&at,  g_attn);
    cudaGetSymbolAddress((void**)&x1,  g_x1);
    cudaGetSymbolAddress((void**)&hid, g_hid);

    const int MB = (M_TOT + 127) / 128;   // 208

    // query = src + pos
    int n4 = M_TOT * D_T / 4;
    add_vec<<<(n4 + 255) / 256, 256>>>(src, pos, q, n4);

    // value = src @ Wv + bv
    sgemm<0><<<dim3(D_T / 64, MB), 256>>>(src, Wv, bv, nullptr, v, M_TOT, D_T, D_T);
    // off = query @ Woff + boff
    sgemm<0><<<dim3(256 / 64, MB), 256>>>(q, Woff, boff, nullptr, off, M_TOT, 256, D_T);
    // attn logits = query @ Wattn + battn
    sgemm<0><<<dim3(128 / 64, MB), 256>>>(q, Wattn, battn, nullptr, aw, M_TOT, 128, D_T);

    // softmax over 16 per (b,l,h)
    softmax16<<<(M_TOT * NH_T + 255) / 256, 256>>>(aw);

    // deformable sampling -> at [M,256]
    {
        long threads = (long)M_TOT * NH_T * 32;
        deform_sample<<<(unsigned)((threads + 255) / 256), 256>>>(v, off, aw, ref, at);
    }

    // src2 + residual: tmp(q) = at @ Wout + bout + src
    sgemm<2><<<dim3(D_T / 64, MB), 256>>>(at, Wout, bout, src, q, M_TOT, D_T, D_T);
    // x1 = LN(tmp)
    ln_warp<<<(M_TOT * 32 + 255) / 256, 256>>>(q, gm1, be1, x1);

    // hid = relu(x1 @ W1 + b1)
    sgemm<1><<<dim3(DFF_T / 64, MB), 256>>>(x1, W1, b1, nullptr, hid, M_TOT, DFF_T, D_T);
    // tmp(v) = hid @ W2 + b2 + x1
    sgemm<2><<<dim3(D_T / 64, MB), 256>>>(hid, W2, b2, x1, v, M_TOT, D_T, DFF_T);
    // out = LN(tmp)
    ln_warp<<<(M_TOT * 32 + 255) / 256, 256>>>(v, gm2, be2, out);
}

// round 4
// speedup vs baseline: 1.5970x; 1.5970x over previous
#include <cuda_runtime.h>
#include <cstdint>

#define LEN_T 13294
#define B_T 2
#define M_TOT (B_T * LEN_T)   // 26588
#define D_T 256
#define NH_T 8
#define DFF_T 1024

// ---------------- scratch (static device globals; no allocation) ----------------
__device__ float g_query[(size_t)M_TOT * D_T];   // rounded q (GEMM A)
__device__ float g_srcr [(size_t)M_TOT * D_T];   // rounded src (GEMM A)
__device__ float g_value[(size_t)M_TOT * D_T];
__device__ float g_off  [(size_t)M_TOT * D_T];
__device__ float g_attw [(size_t)M_TOT * 128];
__device__ float g_attn [(size_t)M_TOT * D_T];   // rounded sampling output
__device__ float g_x1   [(size_t)M_TOT * D_T];   // fp32 (residual)
__device__ float g_x1r  [(size_t)M_TOT * D_T];   // rounded (GEMM A)
__device__ float g_hid  [(size_t)M_TOT * DFF_T]; // rounded (EPI=1)
__device__ float g_tmp  [(size_t)M_TOT * D_T];
__device__ float g_wt   [753664];                // transposed+rounded weights

// ---------------- tf32 helpers ----------------
__device__ __forceinline__ uint32_t f2tf32(float x) {
    uint32_t r;
    asm("cvt.rna.tf32.f32 %0, %1;" : "=r"(r) : "f"(x));
    return r;
}
__device__ __forceinline__ float f2tf32f(float x) {
    return __uint_as_float(f2tf32(x));
}
__device__ __forceinline__ void mma_tf32(float* c, const uint32_t* a, uint32_t b0, uint32_t b1) {
    asm volatile(
        "mma.sync.aligned.m16n8k8.row.col.f32.tf32.tf32.f32 "
        "{%0,%1,%2,%3}, {%4,%5,%6,%7}, {%8,%9}, {%0,%1,%2,%3};"
        : "+f"(c[0]), "+f"(c[1]), "+f"(c[2]), "+f"(c[3])
        : "r"(a[0]), "r"(a[1]), "r"(a[2]), "r"(a[3]), "r"(b0), "r"(b1));
}

// ================= tf32 mma.sync GEMM =================
// C[M,N] = A[M,K] @ Bt[N,K]^T + bias  (EPI: 0 bias, 1 bias+relu+round, 2 bias+residual)
// CTA 128x128, BK=32, 8 warps (4m x 2n), warp tile 32x64.
// SMEM layout: [row][perm(k)] with perm(k)=8*(k>>3) + 2*(k&3) + ((k>>2)&1), row stride 36.
#define SMS 36

template <int EPI>
__global__ void __launch_bounds__(256, 2)
tgemm(const float* __restrict__ A, const float* __restrict__ Bt,
      const float* __restrict__ bias, const float* __restrict__ res,
      float* __restrict__ C, int M, int N, int K)
{
    __shared__ uint32_t As[128 * SMS];
    __shared__ uint32_t Bs[128 * SMS];

    const int tid = threadIdx.x;
    const int wid = tid >> 5, lane = tid & 31;
    const int g = lane >> 2, t = lane & 3;          // groupID, thread-in-group
    const int wm = wid & 3, wn = wid >> 2;          // warp m-tile(32), n-tile(64)
    const int bm = blockIdx.y * 128, bn = blockIdx.x * 128;

    float c[2][8][4];
#pragma unroll
    for (int i = 0; i < 2; i++)
#pragma unroll
        for (int j = 0; j < 8; j++)
#pragma unroll
            for (int e = 0; e < 4; e++) c[i][j][e] = 0.f;

    const int KT = K >> 5;
    for (int kt = 0; kt < KT; kt++) {
        __syncthreads();   // previous compute done before overwrite
        const int k0 = kt << 5;
        // A tile: 128 rows x 32 k (4 float4 per thread)
#pragma unroll
        for (int i = 0; i < 4; i++) {
            int idx = tid + i * 256;
            int row = idx >> 3, c4 = idx & 7;
            float4 v = make_float4(0.f, 0.f, 0.f, 0.f);
            int ga = bm + row;
            if (ga < M) v = *(const float4*)(A + (size_t)ga * K + k0 + c4 * 4);
            uint32_t* dst = &As[row * SMS + (c4 >> 1) * 8 + (c4 & 1)];
            dst[0] = f2tf32(v.x); dst[2] = f2tf32(v.y);
            dst[4] = f2tf32(v.z); dst[6] = f2tf32(v.w);
        }
        // B tile: 128 n-rows x 32 k
#pragma unroll
        for (int i = 0; i < 4; i++) {
            int idx = tid + i * 256;
            int row = idx >> 3, c4 = idx & 7;
            float4 v = *(const float4*)(Bt + (size_t)(bn + row) * K + k0 + c4 * 4);
            uint32_t* dst = &Bs[row * SMS + (c4 >> 1) * 8 + (c4 & 1)];
            dst[0] = f2tf32(v.x); dst[2] = f2tf32(v.y);
            dst[4] = f2tf32(v.z); dst[6] = f2tf32(v.w);
        }
        __syncthreads();

#pragma unroll
        for (int ks = 0; ks < 4; ks++) {
            const int kb = ks * 8 + 2 * t;
            uint32_t a[2][4];
#pragma unroll
            for (int i = 0; i < 2; i++) {
                int m = wm * 32 + i * 16;
                uint2 lo = *(const uint2*)&As[(m + g) * SMS + kb];
                uint2 hi = *(const uint2*)&As[(m + g + 8) * SMS + kb];
                a[i][0] = lo.x; a[i][2] = lo.y;
                a[i][1] = hi.x; a[i][3] = hi.y;
            }
#pragma unroll
            for (int j = 0; j < 8; j++) {
                int n = wn * 64 + j * 8;
                uint2 bb = *(const uint2*)&Bs[(n + g) * SMS + kb];
                mma_tf32(c[0][j], a[0], bb.x, bb.y);
                mma_tf32(c[1][j], a[1], bb.x, bb.y);
            }
        }
    }

    // epilogue
#pragma unroll
    for (int j = 0; j < 8; j++) {
        int col = bn + wn * 64 + j * 8 + t * 2;
        float2 bv = *(const float2*)(bias + col);
#pragma unroll
        for (int i = 0; i < 2; i++) {
            int r0 = bm + wm * 32 + i * 16 + g;
#pragma unroll
            for (int h = 0; h < 2; h++) {
                int row = r0 + h * 8;
                if (row < M) {
                    float o0 = c[i][j][h * 2 + 0] + bv.x;
                    float o1 = c[i][j][h * 2 + 1] + bv.y;
                    if (EPI == 1) {
                        o0 = f2tf32f(fmaxf(o0, 0.f));
                        o1 = f2tf32f(fmaxf(o1, 0.f));
                    }
                    if (EPI == 2) {
                        float2 rr = *(const float2*)(res + (size_t)row * N + col);
                        o0 += rr.x; o1 += rr.y;
                    }
                    *(float2*)(C + (size_t)row * N + col) = make_float2(o0, o1);
                }
            }
        }
    }
}

// ---------------- weight transpose + tf32 round: in[K,N] -> out[N,K] ----------------
__global__ void transpose_k(const float* __restrict__ in, float* __restrict__ out,
                            int K, int N)
{
    __shared__ float tb[32][33];
    int k0 = blockIdx.y * 32, n0 = blockIdx.x * 32;
    int x = threadIdx.x, y = threadIdx.y;
#pragma unroll
    for (int i = 0; i < 32; i += 8)
        tb[y + i][x] = in[(size_t)(k0 + y + i) * N + n0 + x];
    __syncthreads();
#pragma unroll
    for (int i = 0; i < 32; i += 8)
        out[(size_t)(n0 + y + i) * K + k0 + x] = f2tf32f(tb[x][y + i]);
}

// ---------------- q = round(src+pos); srcr = round(src) ----------------
__global__ void add_round(const float* __restrict__ a, const float* __restrict__ b,
                          float* __restrict__ q, float* __restrict__ sr, int n4) {
    int i = blockIdx.x * blockDim.x + threadIdx.x;
    if (i >= n4) return;
    float4 x = ((const float4*)a)[i];
    float4 y = ((const float4*)b)[i];
    ((float4*)q)[i] = make_float4(f2tf32f(x.x + y.x), f2tf32f(x.y + y.y),
                                  f2tf32f(x.z + y.z), f2tf32f(x.w + y.w));
    ((float4*)sr)[i] = make_float4(f2tf32f(x.x), f2tf32f(x.y),
                                   f2tf32f(x.z), f2tf32f(x.w));
}

// ---------------- softmax over 16 (per b,l,h) in place ----------------
__global__ void softmax16(float* __restrict__ a) {
    int r = blockIdx.x * blockDim.x + threadIdx.x;
    if (r >= M_TOT * NH_T) return;
    float* p = a + (size_t)r * 16;
    float v[16], mx = -1e30f;
#pragma unroll
    for (int i = 0; i < 16; i++) { v[i] = p[i]; mx = fmaxf(mx, v[i]); }
    float s = 0.f;
#pragma unroll
    for (int i = 0; i < 16; i++) { v[i] = __expf(v[i] - mx); s += v[i]; }
    float inv = 1.f / s;
#pragma unroll
    for (int i = 0; i < 16; i++) p[i] = v[i] * inv;
}

// ---------------- deformable sampling: warp per (b,l,h), lane = channel ----------------
__global__ void __launch_bounds__(256)
deform_sample(const float* __restrict__ value, const float* __restrict__ off,
              const float* __restrict__ attw, const float* __restrict__ ref,
              float* __restrict__ out)
{
    const int cH[4] = {100, 50, 25, 13};
    const int cW[4] = {100, 50, 25, 13};
    const int cS[4] = {0, 10000, 12500, 13125};

    int tt = blockIdx.x * blockDim.x + threadIdx.x;
    int warp = tt >> 5, lane = tt & 31;
    if (warp >= M_TOT * NH_T) return;
    int h = warp & 7;
    int m = warp >> 3;
    int b = m / LEN_T;

    const float* offp = off  + (size_t)m * 256 + h * 32;
    const float* awp  = attw + (size_t)warp * 16;
    const float* refp = ref  + (size_t)m * 8;
    const float* vb   = value + (size_t)b * LEN_T * 256 + h * 32 + lane;

    float acc = 0.f;
#pragma unroll
    for (int lvl = 0; lvl < 4; lvl++) {
        const int H = cH[lvl], W = cW[lvl];
        const float* vl = vb + (size_t)cS[lvl] * 256;
        float rx = refp[lvl * 2], ry = refp[lvl * 2 + 1];
        float bx = rx * (float)W - 0.5f;
        float by = ry * (float)H - 0.5f;
#pragma unroll
        for (int p = 0; p < 4; p++) {
            float x = bx + offp[(lvl * 4 + p) * 2];
            float y = by + offp[(lvl * 4 + p) * 2 + 1];
            float aw = awp[lvl * 4 + p];
            float xf = floorf(x), yf = floorf(y);
            float dx = x - xf, dy = y - yf;
            int x0 = (int)xf, y0 = (int)yf;
            float w00 = (1.f - dx) * (1.f - dy) * aw;
            float w10 = dx * (1.f - dy) * aw;
            float w01 = (1.f - dx) * dy * aw;
            float w11 = dx * dy * aw;
            bool ix0 = (unsigned)x0 < (unsigned)W;
            bool ix1 = (unsigned)(x0 + 1) < (unsigned)W;
            bool iy0 = (unsigned)y0 < (unsigned)H;
            bool iy1 = (unsigned)(y0 + 1) < (unsigned)H;
            if (ix0 && iy0) acc += w00 * vl[(size_t)(y0 * W + x0) * 256];
            if (ix1 && iy0) acc += w10 * vl[(size_t)(y0 * W + x0 + 1) * 256];
            if (ix0 && iy1) acc += w01 * vl[(size_t)((y0 + 1) * W + x0) * 256];
            if (ix1 && iy1) acc += w11 * vl[(size_t)((y0 + 1) * W + x0 + 1) * 256];
        }
    }
    out[(size_t)warp * 32 + lane] = f2tf32f(acc);
}

// ---------------- layernorm: warp per row of 256 (optional rounded copy) ----------------
__global__ void ln_warp(const float* __restrict__ x, const float* __restrict__ g,
                        const float* __restrict__ b, float* __restrict__ o,
                        float* __restrict__ orr)
{
    int t = blockIdx.x * blockDim.x + threadIdx.x;
    int warp = t >> 5, lane = t & 31;
    if (warp >= M_TOT) return;
    const float4* row = (const float4*)(x + (size_t)warp * 256);
    float4 v0 = row[lane];
    float4 v1 = row[lane + 32];
    float s = v0.x + v0.y + v0.z + v0.w + v1.x + v1.y + v1.z + v1.w;
#pragma unroll
    for (int off = 16; off; off >>= 1) s += __shfl_xor_sync(0xffffffffu, s, off);
    float mean = s * (1.f / 256.f);
    float d[8] = {v0.x - mean, v0.y - mean, v0.z - mean, v0.w - mean,
                  v1.x - mean, v1.y - mean, v1.z - mean, v1.w - mean};
    float ss = 0.f;
#pragma unroll
    for (int i = 0; i < 8; i++) ss += d[i] * d[i];
#pragma unroll
    for (int off = 16; off; off >>= 1) ss += __shfl_xor_sync(0xffffffffu, ss, off);
    float rs = rsqrtf(ss * (1.f / 256.f) + 1e-5f);
    const float4* g4 = (const float4*)g;
    const float4* b4 = (const float4*)b;
    float4 G0 = g4[lane], G1 = g4[lane + 32];
    float4 B0 = b4[lane], B1 = b4[lane + 32];
    float4 o0 = make_float4(d[0] * rs * G0.x + B0.x, d[1] * rs * G0.y + B0.y,
                            d[2] * rs * G0.z + B0.z, d[3] * rs * G0.w + B0.w);
    float4 o1 = make_float4(d[4] * rs * G1.x + B1.x, d[5] * rs * G1.y + B1.y,
                            d[6] * rs * G1.z + B1.z, d[7] * rs * G1.w + B1.w);
    float4* orow = (float4*)(o + (size_t)warp * 256);
    orow[lane] = o0;
    orow[lane + 32] = o1;
    if (orr) {
        float4 r0 = make_float4(f2tf32f(o0.x), f2tf32f(o0.y), f2tf32f(o0.z), f2tf32f(o0.w));
        float4 r1 = make_float4(f2tf32f(o1.x), f2tf32f(o1.y), f2tf32f(o1.z), f2tf32f(o1.w));
        float4* rrow = (float4*)(orr + (size_t)warp * 256);
        rrow[lane] = r0;
        rrow[lane + 32] = r1;
    }
}

// ---------------- launch ----------------
extern "C" void kernel_launch(void* const* d_in, const int* in_sizes, int n_in,
                              void* d_out, int out_size)
{
    const float* src   = (const float*)d_in[0];
    const float* pos   = (const float*)d_in[1];
    const float* ref   = (const float*)d_in[2];
    const float* Wv    = (const float*)d_in[3];
    const float* bv    = (const float*)d_in[4];
    const float* Woff  = (const float*)d_in[5];
    const float* boff  = (const float*)d_in[6];
    const float* Wattn = (const float*)d_in[7];
    const float* battn = (const float*)d_in[8];
    const float* Wout  = (const float*)d_in[9];
    const float* bout  = (const float*)d_in[10];
    const float* W1    = (const float*)d_in[11];
    const float* b1    = (const float*)d_in[12];
    const float* W2    = (const float*)d_in[13];
    const float* b2    = (const float*)d_in[14];
    const float* gm1   = (const float*)d_in[15];
    const float* be1   = (const float*)d_in[16];
    const float* gm2   = (const float*)d_in[17];
    const float* be2   = (const float*)d_in[18];
    float* out = (float*)d_out;

    float *q, *sr, *v, *off, *aw, *at, *x1, *x1r, *hid, *tmp, *wt;
    cudaGetSymbolAddress((void**)&q,   g_query);
    cudaGetSymbolAddress((void**)&sr,  g_srcr);
    cudaGetSymbolAddress((void**)&v,   g_value);
    cudaGetSymbolAddress((void**)&off, g_off);
    cudaGetSymbolAddress((void**)&aw,  g_attw);
    cudaGetSymbolAddress((void**)&at,  g_attn);
    cudaGetSymbolAddress((void**)&x1,  g_x1);
    cudaGetSymbolAddress((void**)&x1r, g_x1r);
    cudaGetSymbolAddress((void**)&hid, g_hid);
    cudaGetSymbolAddress((void**)&tmp, g_tmp);
    cudaGetSymbolAddress((void**)&wt,  g_wt);

    float* wtv    = wt + 0;
    float* wtoff  = wt + 65536;
    float* wtattn = wt + 131072;
    float* wtout  = wt + 163840;
    float* wt1    = wt + 229376;
    float* wt2    = wt + 491520;

    const int MB = (M_TOT + 127) / 128;   // 208
    dim3 tb(32, 8);

    // q = round(src+pos); srcr = round(src)
    int n4 = M_TOT * D_T / 4;
    add_round<<<(n4 + 255) / 256, 256>>>(src, pos, q, sr, n4);

    // transpose+round weights to [N,K]
    transpose_k<<<dim3(8, 8),  tb>>>(Wv,    wtv,    256, 256);
    transpose_k<<<dim3(8, 8),  tb>>>(Woff,  wtoff,  256, 256);
    transpose_k<<<dim3(4, 8),  tb>>>(Wattn, wtattn, 256, 128);
    transpose_k<<<dim3(8, 8),  tb>>>(Wout,  wtout,  256, 256);
    transpose_k<<<dim3(32, 8), tb>>>(W1,    wt1,    256, 1024);
    transpose_k<<<dim3(8, 32), tb>>>(W2,    wt2,    1024, 256);

    // value = srcr @ Wv + bv
    tgemm<0><<<dim3(2, MB), 256>>>(sr, wtv, bv, nullptr, v, M_TOT, 256, 256);
    // off = q @ Woff + boff
    tgemm<0><<<dim3(2, MB), 256>>>(q, wtoff, boff, nullptr, off, M_TOT, 256, 256);
    // attn logits = q @ Wattn + battn
    tgemm<0><<<dim3(1, MB), 256>>>(q, wtattn, battn, nullptr, aw, M_TOT, 128, 256);

    softmax16<<<(M_TOT * NH_T + 255) / 256, 256>>>(aw);

    {
        long threads = (long)M_TOT * NH_T * 32;
        deform_sample<<<(unsigned)((threads + 255) / 256), 256>>>(v, off, aw, ref, at);
    }

    // out-proj + residual -> tmp
    tgemm<2><<<dim3(2, MB), 256>>>(at, wtout, bout, src, tmp, M_TOT, 256, 256);
    ln_warp<<<(M_TOT * 32 + 255) / 256, 256>>>(tmp, gm1, be1, x1, x1r);

    // FFN
    tgemm<1><<<dim3(8, MB), 256>>>(x1r, wt1, b1, nullptr, hid, M_TOT, 1024, 256);
    tgemm<2><<<dim3(2, MB), 256>>>(hid, wt2, b2, x1, tmp, M_TOT, 256, 1024);
    ln_warp<<<(M_TOT * 32 + 255) / 256, 256>>>(tmp, gm2, be2, out, nullptr);
}

// round 5
// speedup vs baseline: 1.7703x; 1.1086x over previous
#include <cuda_runtime.h>
#include <cuda_fp16.h>
#include <cstdint>

#define LEN_T 13294
#define B_T 2
#define M_TOT (B_T * LEN_T)   // 26588
#define D_T 256
#define NH_T 8
#define DFF_T 1024

// ---------------- scratch (static device globals; no allocation) ----------------
__device__ float  g_query[(size_t)M_TOT * D_T];   // rounded q (GEMM A)
__device__ float  g_srcr [(size_t)M_TOT * D_T];   // rounded src (GEMM A)
__device__ __half g_valh [(size_t)M_TOT * D_T];   // value in fp16
__device__ float  g_off  [(size_t)M_TOT * D_T];
__device__ float  g_attw [(size_t)M_TOT * 128];
__device__ float  g_attn [(size_t)M_TOT * D_T];   // rounded sampling output
__device__ float  g_x1   [(size_t)M_TOT * D_T];   // fp32 (residual)
__device__ float  g_x1r  [(size_t)M_TOT * D_T];   // rounded (GEMM A)
__device__ float  g_hid  [(size_t)M_TOT * DFF_T]; // rounded (EPI=1)
__device__ float  g_tmp  [(size_t)M_TOT * D_T];
__device__ float  g_wt   [753664];                // transposed+rounded weights

// ---------------- tf32 helpers ----------------
__device__ __forceinline__ uint32_t f2tf32(float x) {
    uint32_t r;
    asm("cvt.rna.tf32.f32 %0, %1;" : "=r"(r) : "f"(x));
    return r;
}
__device__ __forceinline__ float f2tf32f(float x) {
    return __uint_as_float(f2tf32(x));
}
__device__ __forceinline__ void mma_tf32(float* c, const uint32_t* a, uint32_t b0, uint32_t b1) {
    asm volatile(
        "mma.sync.aligned.m16n8k8.row.col.f32.tf32.tf32.f32 "
        "{%0,%1,%2,%3}, {%4,%5,%6,%7}, {%8,%9}, {%0,%1,%2,%3};"
        : "+f"(c[0]), "+f"(c[1]), "+f"(c[2]), "+f"(c[3])
        : "r"(a[0]), "r"(a[1]), "r"(a[2]), "r"(a[3]), "r"(b0), "r"(b1));
}

// ================= tf32 mma.sync GEMM =================
// C[M,N] = A[M,K] @ Bt[N,K]^T + bias
// EPI: 0 bias->f32, 1 bias+relu+round->f32, 2 bias+residual->f32, 3 bias->f16
// CTA 128x128, BK=32, 8 warps (4m x 2n), warp tile 32x64.
// A/B must be PRE-ROUNDED to tf32 by producers (loader is a pure permuted copy).
#define SMS 36

template <int EPI>
__global__ void __launch_bounds__(256, 2)
tgemm(const float* __restrict__ A, const float* __restrict__ Bt,
      const float* __restrict__ bias, const float* __restrict__ res,
      void* __restrict__ Cv, int M, int N, int K)
{
    __shared__ uint32_t As[128 * SMS];
    __shared__ uint32_t Bs[128 * SMS];

    const int tid = threadIdx.x;
    const int wid = tid >> 5, lane = tid & 31;
    const int g = lane >> 2, t = lane & 3;
    const int wm = wid & 3, wn = wid >> 2;
    const int bm = blockIdx.y * 128, bn = blockIdx.x * 128;

    float c[2][8][4];
#pragma unroll
    for (int i = 0; i < 2; i++)
#pragma unroll
        for (int j = 0; j < 8; j++)
#pragma unroll
            for (int e = 0; e < 4; e++) c[i][j][e] = 0.f;

    const int KT = K >> 5;
    for (int kt = 0; kt < KT; kt++) {
        __syncthreads();
        const int k0 = kt << 5;
#pragma unroll
        for (int i = 0; i < 4; i++) {
            int idx = tid + i * 256;
            int row = idx >> 3, c4 = idx & 7;
            float4 v = make_float4(0.f, 0.f, 0.f, 0.f);
            int ga = bm + row;
            if (ga < M) v = *(const float4*)(A + (size_t)ga * K + k0 + c4 * 4);
            uint32_t* dst = &As[row * SMS + (c4 >> 1) * 8 + (c4 & 1)];
            dst[0] = __float_as_uint(v.x); dst[2] = __float_as_uint(v.y);
            dst[4] = __float_as_uint(v.z); dst[6] = __float_as_uint(v.w);
        }
#pragma unroll
        for (int i = 0; i < 4; i++) {
            int idx = tid + i * 256;
            int row = idx >> 3, c4 = idx & 7;
            float4 v = *(const float4*)(Bt + (size_t)(bn + row) * K + k0 + c4 * 4);
            uint32_t* dst = &Bs[row * SMS + (c4 >> 1) * 8 + (c4 & 1)];
            dst[0] = __float_as_uint(v.x); dst[2] = __float_as_uint(v.y);
            dst[4] = __float_as_uint(v.z); dst[6] = __float_as_uint(v.w);
        }
        __syncthreads();

#pragma unroll
        for (int ks = 0; ks < 4; ks++) {
            const int kb = ks * 8 + 2 * t;
            uint32_t a[2][4];
#pragma unroll
            for (int i = 0; i < 2; i++) {
                int m = wm * 32 + i * 16;
                uint2 lo = *(const uint2*)&As[(m + g) * SMS + kb];
                uint2 hi = *(const uint2*)&As[(m + g + 8) * SMS + kb];
                a[i][0] = lo.x; a[i][2] = lo.y;
                a[i][1] = hi.x; a[i][3] = hi.y;
            }
#pragma unroll
            for (int j = 0; j < 8; j++) {
                int n = wn * 64 + j * 8;
                uint2 bb = *(const uint2*)&Bs[(n + g) * SMS + kb];
                mma_tf32(c[0][j], a[0], bb.x, bb.y);
                mma_tf32(c[1][j], a[1], bb.x, bb.y);
            }
        }
    }

    // epilogue
#pragma unroll
    for (int j = 0; j < 8; j++) {
        int col = bn + wn * 64 + j * 8 + t * 2;
        float2 bv = *(const float2*)(bias + col);
#pragma unroll
        for (int i = 0; i < 2; i++) {
            int r0 = bm + wm * 32 + i * 16 + g;
#pragma unroll
            for (int h = 0; h < 2; h++) {
                int row = r0 + h * 8;
                if (row < M) {
                    float o0 = c[i][j][h * 2 + 0] + bv.x;
                    float o1 = c[i][j][h * 2 + 1] + bv.y;
                    if (EPI == 1) {
                        o0 = f2tf32f(fmaxf(o0, 0.f));
                        o1 = f2tf32f(fmaxf(o1, 0.f));
                    }
                    if (EPI == 2) {
                        float2 rr = *(const float2*)(res + (size_t)row * N + col);
                        o0 += rr.x; o1 += rr.y;
                    }
                    if (EPI == 3) {
                        *(__half2*)((__half*)Cv + (size_t)row * N + col) =
                            __floats2half2_rn(o0, o1);
                    } else {
                        *(float2*)((float*)Cv + (size_t)row * N + col) =
                            make_float2(o0, o1);
                    }
                }
            }
        }
    }
}

// ---------------- weight transpose + tf32 round: in[K,N] -> out[N,K] ----------------
__global__ void transpose_k(const float* __restrict__ in, float* __restrict__ out,
                            int K, int N)
{
    __shared__ float tb[32][33];
    int k0 = blockIdx.y * 32, n0 = blockIdx.x * 32;
    int x = threadIdx.x, y = threadIdx.y;
#pragma unroll
    for (int i = 0; i < 32; i += 8)
        tb[y + i][x] = in[(size_t)(k0 + y + i) * N + n0 + x];
    __syncthreads();
#pragma unroll
    for (int i = 0; i < 32; i += 8)
        out[(size_t)(n0 + y + i) * K + k0 + x] = f2tf32f(tb[x][y + i]);
}

// ---------------- q = round(src+pos); srcr = round(src) ----------------
__global__ void add_round(const float* __restrict__ a, const float* __restrict__ b,
                          float* __restrict__ q, float* __restrict__ sr, int n4) {
    int i = blockIdx.x * blockDim.x + threadIdx.x;
    if (i >= n4) return;
    float4 x = ((const float4*)a)[i];
    float4 y = ((const float4*)b)[i];
    ((float4*)q)[i] = make_float4(f2tf32f(x.x + y.x), f2tf32f(x.y + y.y),
                                  f2tf32f(x.z + y.z), f2tf32f(x.w + y.w));
    ((float4*)sr)[i] = make_float4(f2tf32f(x.x), f2tf32f(x.y),
                                   f2tf32f(x.z), f2tf32f(x.w));
}

// ---------------- softmax over 16 (per b,l,h) in place ----------------
__global__ void softmax16(float* __restrict__ a) {
    int r = blockIdx.x * blockDim.x + threadIdx.x;
    if (r >= M_TOT * NH_T) return;
    float* p = a + (size_t)r * 16;
    float v[16], mx = -1e30f;
#pragma unroll
    for (int i = 0; i < 16; i++) { v[i] = p[i]; mx = fmaxf(mx, v[i]); }
    float s = 0.f;
#pragma unroll
    for (int i = 0; i < 16; i++) { v[i] = __expf(v[i] - mx); s += v[i]; }
    float inv = 1.f / s;
#pragma unroll
    for (int i = 0; i < 16; i++) p[i] = v[i] * inv;
}

// ---------------- deformable sampling (fp16 value, 2 points per warp pass) --------
// warp per (b,l,h). Lane: pp = lane>>4 selects point parity, c = lane&15 = channel pair.
// Each lane accumulates float2 (channels c*2, c*2+1). shfl_xor(16) merges the two
// point-groups; lanes 0-15 write the 32 output channels.
__global__ void __launch_bounds__(256)
deform_sample(const __half* __restrict__ value, const float* __restrict__ off,
              const float* __restrict__ attw, const float* __restrict__ ref,
              float* __restrict__ out)
{
    const int cH[4] = {100, 50, 25, 13};
    const int cW[4] = {100, 50, 25, 13};
    const int cS[4] = {0, 10000, 12500, 13125};

    int tt = blockIdx.x * blockDim.x + threadIdx.x;
    int warp = tt >> 5, lane = tt & 31;
    if (warp >= M_TOT * NH_T) return;
    int pp = lane >> 4, c = lane & 15;
    int h = warp & 7;
    int m = warp >> 3;
    int b = m / LEN_T;

    const float*  offp = off  + (size_t)m * 256 + h * 32;
    const float*  awp  = attw + (size_t)warp * 16;
    const float*  refp = ref  + (size_t)m * 8;
    const __half* vb   = value + (size_t)b * LEN_T * 256 + h * 32 + c * 2;

    float accx = 0.f, accy = 0.f;
#pragma unroll
    for (int lvl = 0; lvl < 4; lvl++) {
        const int H = cH[lvl], W = cW[lvl];
        const __half* vl = vb + (size_t)cS[lvl] * 256;
        float rx = refp[lvl * 2], ry = refp[lvl * 2 + 1];
        float bx = rx * (float)W - 0.5f;
        float by = ry * (float)H - 0.5f;
#pragma unroll
        for (int it = 0; it < 2; it++) {
            int p = it * 2 + pp;                 // point within level
            float x = bx + offp[(lvl * 4 + p) * 2];
            float y = by + offp[(lvl * 4 + p) * 2 + 1];
            float aw = awp[lvl * 4 + p];
            float xf = floorf(x), yf = floorf(y);
            float dx = x - xf, dy = y - yf;
            int x0 = (int)xf, y0 = (int)yf;
            float w00 = (1.f - dx) * (1.f - dy) * aw;
            float w10 = dx * (1.f - dy) * aw;
            float w01 = (1.f - dx) * dy * aw;
            float w11 = dx * dy * aw;
            bool ix0 = (unsigned)x0 < (unsigned)W;
            bool ix1 = (unsigned)(x0 + 1) < (unsigned)W;
            bool iy0 = (unsigned)y0 < (unsigned)H;
            bool iy1 = (unsigned)(y0 + 1) < (unsigned)H;
            if (ix0 && iy0) {
                float2 f = __half22float2(*(const __half2*)(vl + (size_t)(y0 * W + x0) * 256));
                accx += w00 * f.x; accy += w00 * f.y;
            }
            if (ix1 && iy0) {
                float2 f = __half22float2(*(const __half2*)(vl + (size_t)(y0 * W + x0 + 1) * 256));
                accx += w10 * f.x; accy += w10 * f.y;
            }
            if (ix0 && iy1) {
                float2 f = __half22float2(*(const __half2*)(vl + (size_t)((y0 + 1) * W + x0) * 256));
                accx += w01 * f.x; accy += w01 * f.y;
            }
            if (ix1 && iy1) {
                float2 f = __half22float2(*(const __half2*)(vl + (size_t)((y0 + 1) * W + x0 + 1) * 256));
                accx += w11 * f.x; accy += w11 * f.y;
            }
        }
    }
    accx += __shfl_xor_sync(0xffffffffu, accx, 16);
    accy += __shfl_xor_sync(0xffffffffu, accy, 16);
    if (pp == 0) {
        *(float2*)(out + (size_t)warp * 32 + c * 2) =
            make_float2(f2tf32f(accx), f2tf32f(accy));
    }
}

// ---------------- layernorm: warp per row of 256 (optional rounded copy) ----------------
__global__ void ln_warp(const float* __restrict__ x, const float* __restrict__ g,
                        const float* __restrict__ b, float* __restrict__ o,
                        float* __restrict__ orr)
{
    int t = blockIdx.x * blockDim.x + threadIdx.x;
    int warp = t >> 5, lane = t & 31;
    if (warp >= M_TOT) return;
    const float4* row = (const float4*)(x + (size_t)warp * 256);
    float4 v0 = row[lane];
    float4 v1 = row[lane + 32];
    float s = v0.x + v0.y + v0.z + v0.w + v1.x + v1.y + v1.z + v1.w;
#pragma unroll
    for (int off = 16; off; off >>= 1) s += __shfl_xor_sync(0xffffffffu, s, off);
    float mean = s * (1.f / 256.f);
    float d[8] = {v0.x - mean, v0.y - mean, v0.z - mean, v0.w - mean,
                  v1.x - mean, v1.y - mean, v1.z - mean, v1.w - mean};
    float ss = 0.f;
#pragma unroll
    for (int i = 0; i < 8; i++) ss += d[i] * d[i];
#pragma unroll
    for (int off = 16; off; off >>= 1) ss += __shfl_xor_sync(0xffffffffu, ss, off);
    float rs = rsqrtf(ss * (1.f / 256.f) + 1e-5f);
    const float4* g4 = (const float4*)g;
    const float4* b4 = (const float4*)b;
    float4 G0 = g4[lane], G1 = g4[lane + 32];
    float4 B0 = b4[lane], B1 = b4[lane + 32];
    float4 o0 = make_float4(d[0] * rs * G0.x + B0.x, d[1] * rs * G0.y + B0.y,
                            d[2] * rs * G0.z + B0.z, d[3] * rs * G0.w + B0.w);
    float4 o1 = make_float4(d[4] * rs * G1.x + B1.x, d[5] * rs * G1.y + B1.y,
                            d[6] * rs * G1.z + B1.z, d[7] * rs * G1.w + B1.w);
    float4* orow = (float4*)(o + (size_t)warp * 256);
    orow[lane] = o0;
    orow[lane + 32] = o1;
    if (orr) {
        float4 r0 = make_float4(f2tf32f(o0.x), f2tf32f(o0.y), f2tf32f(o0.z), f2tf32f(o0.w));
        float4 r1 = make_float4(f2tf32f(o1.x), f2tf32f(o1.y), f2tf32f(o1.z), f2tf32f(o1.w));
        float4* rrow = (float4*)(orr + (size_t)warp * 256);
        rrow[lane] = r0;
        rrow[lane + 32] = r1;
    }
}

// ---------------- launch ----------------
extern "C" void kernel_launch(void* const* d_in, const int* in_sizes, int n_in,
                              void* d_out, int out_size)
{
    const float* src   = (const float*)d_in[0];
    const float* pos   = (const float*)d_in[1];
    const float* ref   = (const float*)d_in[2];
    const float* Wv    = (const float*)d_in[3];
    const float* bv    = (const float*)d_in[4];
    const float* Woff  = (const float*)d_in[5];
    const float* boff  = (const float*)d_in[6];
    const float* Wattn = (const float*)d_in[7];
    const float* battn = (const float*)d_in[8];
    const float* Wout  = (const float*)d_in[9];
    const float* bout  = (const float*)d_in[10];
    const float* W1    = (const float*)d_in[11];
    const float* b1    = (const float*)d_in[12];
    const float* W2    = (const float*)d_in[13];
    const float* b2    = (const float*)d_in[14];
    const float* gm1   = (const float*)d_in[15];
    const float* be1   = (const float*)d_in[16];
    const float* gm2   = (const float*)d_in[17];
    const float* be2   = (const float*)d_in[18];
    float* out = (float*)d_out;

    float *q, *sr, *off, *aw, *at, *x1, *x1r, *hid, *tmp, *wt;
    __half* vh;
    cudaGetSymbolAddress((void**)&q,   g_query);
    cudaGetSymbolAddress((void**)&sr,  g_srcr);
    cudaGetSymbolAddress((void**)&vh,  g_valh);
    cudaGetSymbolAddress((void**)&off, g_off);
    cudaGetSymbolAddress((void**)&aw,  g_attw);
    cudaGetSymbolAddress((void**)&at,  g_attn);
    cudaGetSymbolAddress((void**)&x1,  g_x1);
    cudaGetSymbolAddress((void**)&x1r, g_x1r);
    cudaGetSymbolAddress((void**)&hid, g_hid);
    cudaGetSymbolAddress((void**)&tmp, g_tmp);
    cudaGetSymbolAddress((void**)&wt,  g_wt);

    float* wtv    = wt + 0;
    float* wtoff  = wt + 65536;
    float* wtattn = wt + 131072;
    float* wtout  = wt + 163840;
    float* wt1    = wt + 229376;
    float* wt2    = wt + 491520;

    const int MB = (M_TOT + 127) / 128;   // 208
    dim3 tb(32, 8);

    // q = round(src+pos); srcr = round(src)
    int n4 = M_TOT * D_T / 4;
    add_round<<<(n4 + 255) / 256, 256>>>(src, pos, q, sr, n4);

    // transpose+round weights to [N,K]
    transpose_k<<<dim3(8, 8),  tb>>>(Wv,    wtv,    256, 256);
    transpose_k<<<dim3(8, 8),  tb>>>(Woff,  wtoff,  256, 256);
    transpose_k<<<dim3(4, 8),  tb>>>(Wattn, wtattn, 256, 128);
    transpose_k<<<dim3(8, 8),  tb>>>(Wout,  wtout,  256, 256);
    transpose_k<<<dim3(32, 8), tb>>>(W1,    wt1,    256, 1024);
    transpose_k<<<dim3(8, 32), tb>>>(W2,    wt2,    1024, 256);

    // value (fp16) = srcr @ Wv + bv
    tgemm<3><<<dim3(2, MB), 256>>>(sr, wtv, bv, nullptr, vh, M_TOT, 256, 256);
    // off = q @ Woff + boff
    tgemm<0><<<dim3(2, MB), 256>>>(q, wtoff, boff, nullptr, off, M_TOT, 256, 256);
    // attn logits = q @ Wattn + battn
    tgemm<0><<<dim3(1, MB), 256>>>(q, wtattn, battn, nullptr, aw, M_TOT, 128, 256);

    softmax16<<<(M_TOT * NH_T + 255) / 256, 256>>>(aw);

    {
        long threads = (long)M_TOT * NH_T * 32;
        deform_sample<<<(unsigned)((threads + 255) / 256), 256>>>(vh, off, aw, ref, at);
    }

    // out-proj + residual -> tmp
    tgemm<2><<<dim3(2, MB), 256>>>(at, wtout, bout, src, tmp, M_TOT, 256, 256);
    ln_warp<<<(M_TOT * 32 + 255) / 256, 256>>>(tmp, gm1, be1, x1, x1r);

    // FFN
    tgemm<1><<<dim3(8, MB), 256>>>(x1r, wt1, b1, nullptr, hid, M_TOT, 1024, 256);
    tgemm<2><<<dim3(2, MB), 256>>>(hid, wt2, b2, x1, tmp, M_TOT, 256, 1024);
    ln_warp<<<(M_TOT * 32 + 255) / 256, 256>>>(tmp, gm2, be2, out, nullptr);
}

// round 6
// speedup vs baseline: 2.9061x; 1.6415x over previous
#include <cuda_runtime.h>
#include <cuda_fp16.h>
#include <cstdint>

#define LEN_T 13294
#define B_T 2
#define M_TOT (B_T * LEN_T)   // 26588
#define D_T 256
#define NH_T 8
#define DFF_T 1024

// ---------------- scratch (static device globals; no allocation) ----------------
__device__ __half g_qh  [(size_t)M_TOT * D_T];    // fp16 query (GEMM A)
__device__ __half g_srch[(size_t)M_TOT * D_T];    // fp16 src (GEMM A)
__device__ __half g_valh[(size_t)M_TOT * D_T];    // fp16 value
__device__ float  g_off [(size_t)M_TOT * D_T];    // offsets (f32)
__device__ float  g_aw  [(size_t)M_TOT * 128];    // attn logits (f32)
__device__ __half g_ath [(size_t)M_TOT * D_T];    // fp16 sampling output
__device__ float  g_x1  [(size_t)M_TOT * D_T];    // f32 (residual)
__device__ __half g_x1h [(size_t)M_TOT * D_T];    // fp16 copy
__device__ __half g_hidh[(size_t)M_TOT * DFF_T];  // fp16 hidden
__device__ float  g_tmp [(size_t)M_TOT * D_T];
__device__ __half g_wth [753664];                 // fp16 transposed weights

// ================= fp16 mma GEMM =================
// C[M,N] = A[M,K] @ Bt[N,K]^T + bias ; A,Bt fp16, accum f32.
// EPI: 0 bias->f32, 1 bias+relu->f16, 2 bias+residual->f32, 3 bias->f16
// CTA 128x128, BK=32, 8 warps (4m x 2n), warp tile 32x64.
// SMEM: uint32 = half2 k-pair; within each k16 chunk (8 pairs) pair q stored at
// slot 2*(q&3) + (q>>2)  => thread t's uint2 load at slot 2t yields pairs (t, t+4)
// = regs {a0/a2} or {b0/b1} of m16n8k16. Row stride 18 uint32.
#define SMS2 18

__device__ __forceinline__ void mma_f16(float* c, const uint32_t* a, uint32_t b0, uint32_t b1) {
    asm volatile(
        "mma.sync.aligned.m16n8k16.row.col.f32.f16.f16.f32 "
        "{%0,%1,%2,%3}, {%4,%5,%6,%7}, {%8,%9}, {%0,%1,%2,%3};"
        : "+f"(c[0]), "+f"(c[1]), "+f"(c[2]), "+f"(c[3])
        : "r"(a[0]), "r"(a[1]), "r"(a[2]), "r"(a[3]), "r"(b0), "r"(b1));
}

template <int EPI>
__global__ void __launch_bounds__(256, 2)
hgemm(const __half* __restrict__ A, const __half* __restrict__ Bt,
      const float* __restrict__ bias, const float* __restrict__ res,
      void* __restrict__ Cv, int M, int N, int K)
{
    __shared__ uint32_t As[128 * SMS2];
    __shared__ uint32_t Bs[128 * SMS2];

    const int tid = threadIdx.x;
    const int wid = tid >> 5, lane = tid & 31;
    const int g = lane >> 2, t = lane & 3;
    const int wm = wid & 3, wn = wid >> 2;
    const int bm = blockIdx.y * 128, bn = blockIdx.x * 128;

    float c[2][8][4];
#pragma unroll
    for (int i = 0; i < 2; i++)
#pragma unroll
        for (int j = 0; j < 8; j++)
#pragma unroll
            for (int e = 0; e < 4; e++) c[i][j][e] = 0.f;

    const int KT = K >> 5;
    for (int kt = 0; kt < KT; kt++) {
        __syncthreads();
        const int k0 = kt << 5;
        // A tile: 128 rows x 32 halves; 512 uint4 loads, 2 per thread
#pragma unroll
        for (int i = 0; i < 2; i++) {
            int idx = tid + i * 256;
            int row = idx >> 2, v = idx & 3;    // v = uint4 (4 pairs) within row
            uint4 d = make_uint4(0, 0, 0, 0);
            int ga = bm + row;
            if (ga < M) d = *(const uint4*)(A + (size_t)ga * K + k0 + v * 8);
            uint32_t* dst = &As[row * SMS2 + (v >> 1) * 8 + (v & 1)];
            dst[0] = d.x; dst[2] = d.y; dst[4] = d.z; dst[6] = d.w;
        }
#pragma unroll
        for (int i = 0; i < 2; i++) {
            int idx = tid + i * 256;
            int row = idx >> 2, v = idx & 3;
            uint4 d = *(const uint4*)(Bt + (size_t)(bn + row) * K + k0 + v * 8);
            uint32_t* dst = &Bs[row * SMS2 + (v >> 1) * 8 + (v & 1)];
            dst[0] = d.x; dst[2] = d.y; dst[4] = d.z; dst[6] = d.w;
        }
        __syncthreads();

#pragma unroll
        for (int ks = 0; ks < 2; ks++) {
            const int kb = ks * 8 + 2 * t;
            uint32_t a[2][4];
#pragma unroll
            for (int i = 0; i < 2; i++) {
                int m = wm * 32 + i * 16;
                uint2 lo = *(const uint2*)&As[(m + g) * SMS2 + kb];
                uint2 hi = *(const uint2*)&As[(m + g + 8) * SMS2 + kb];
                a[i][0] = lo.x; a[i][1] = hi.x; a[i][2] = lo.y; a[i][3] = hi.y;
            }
#pragma unroll
            for (int j = 0; j < 8; j++) {
                int n = wn * 64 + j * 8;
                uint2 bb = *(const uint2*)&Bs[(n + g) * SMS2 + kb];
                mma_f16(c[0][j], a[0], bb.x, bb.y);
                mma_f16(c[1][j], a[1], bb.x, bb.y);
            }
        }
    }

    // epilogue
#pragma unroll
    for (int j = 0; j < 8; j++) {
        int col = bn + wn * 64 + j * 8 + t * 2;
        float2 bv = *(const float2*)(bias + col);
#pragma unroll
        for (int i = 0; i < 2; i++) {
            int r0 = bm + wm * 32 + i * 16 + g;
#pragma unroll
            for (int h = 0; h < 2; h++) {
                int row = r0 + h * 8;
                if (row < M) {
                    float o0 = c[i][j][h * 2 + 0] + bv.x;
                    float o1 = c[i][j][h * 2 + 1] + bv.y;
                    if (EPI == 1) { o0 = fmaxf(o0, 0.f); o1 = fmaxf(o1, 0.f); }
                    if (EPI == 2) {
                        float2 rr = *(const float2*)(res + (size_t)row * N + col);
                        o0 += rr.x; o1 += rr.y;
                    }
                    if (EPI == 1 || EPI == 3) {
                        *(__half2*)((__half*)Cv + (size_t)row * N + col) =
                            __floats2half2_rn(o0, o1);
                    } else {
                        *(float2*)((float*)Cv + (size_t)row * N + col) =
                            make_float2(o0, o1);
                    }
                }
            }
        }
    }
}

// ---------------- fused weight transpose+fp16: all 6 weights, one launch ----------------
// in[K,N] f32 -> out[N,K] f16.  Tile ranges: Wv 0-63, Woff 64-127, Wattn 128-159,
// Wout 160-223, W1 224-479, W2 480-735.
__global__ void transpose_all(const float* __restrict__ Wv, const float* __restrict__ Woff,
                              const float* __restrict__ Wattn, const float* __restrict__ Wout,
                              const float* __restrict__ W1, const float* __restrict__ W2,
                              __half* __restrict__ ov, __half* __restrict__ ooff,
                              __half* __restrict__ oattn, __half* __restrict__ oout,
                              __half* __restrict__ o1, __half* __restrict__ o2)
{
    __shared__ float tb[32][33];
    int tt = blockIdx.x;
    const float* in; __half* out; int K, N, w;
    if (tt < 64)       { in = Wv;    out = ov;    K = 256;  N = 256;  w = tt; }
    else if (tt < 128) { in = Woff;  out = ooff;  K = 256;  N = 256;  w = tt - 64; }
    else if (tt < 160) { in = Wattn; out = oattn; K = 256;  N = 128;  w = tt - 128; }
    else if (tt < 224) { in = Wout;  out = oout;  K = 256;  N = 256;  w = tt - 160; }
    else if (tt < 480) { in = W1;    out = o1;    K = 256;  N = 1024; w = tt - 224; }
    else               { in = W2;    out = o2;    K = 1024; N = 256;  w = tt - 480; }
    int nt = w % (N >> 5), kt = w / (N >> 5);
    int k0 = kt * 32, n0 = nt * 32;
    int x = threadIdx.x, y = threadIdx.y;
#pragma unroll
    for (int i = 0; i < 32; i += 8)
        tb[y + i][x] = in[(size_t)(k0 + y + i) * N + n0 + x];
    __syncthreads();
#pragma unroll
    for (int i = 0; i < 32; i += 8)
        out[(size_t)(n0 + y + i) * K + k0 + x] = __float2half(tb[x][y + i]);
}

// ---------------- qh = h(src+pos); srch = h(src) ----------------
__global__ void add_half(const float* __restrict__ a, const float* __restrict__ b,
                         __half* __restrict__ q, __half* __restrict__ sr, int n4) {
    int i = blockIdx.x * blockDim.x + threadIdx.x;
    if (i >= n4) return;
    float4 x = ((const float4*)a)[i];
    float4 y = ((const float4*)b)[i];
    ((__half2*)q)[i * 2 + 0] = __floats2half2_rn(x.x + y.x, x.y + y.y);
    ((__half2*)q)[i * 2 + 1] = __floats2half2_rn(x.z + y.z, x.w + y.w);
    ((__half2*)sr)[i * 2 + 0] = __floats2half2_rn(x.x, x.y);
    ((__half2*)sr)[i * 2 + 1] = __floats2half2_rn(x.z, x.w);
}

// ---------------- deformable sampling + fused softmax ----------------
// warp per (b,l,h). pp = lane>>4 point-parity, c = lane&15 channel pair.
// Softmax over 16 logits computed in-warp (16-wide segments).
__global__ void __launch_bounds__(256)
deform_sample(const __half* __restrict__ value, const float* __restrict__ off,
              const float* __restrict__ logits, const float* __restrict__ ref,
              __half* __restrict__ out)
{
    const int cH[4] = {100, 50, 25, 13};
    const int cW[4] = {100, 50, 25, 13};
    const int cS[4] = {0, 10000, 12500, 13125};

    int tt = blockIdx.x * blockDim.x + threadIdx.x;
    int warp = tt >> 5, lane = tt & 31;
    if (warp >= M_TOT * NH_T) return;
    int pp = lane >> 4, c = lane & 15;
    int h = warp & 7;
    int m = warp >> 3;
    int b = m / LEN_T;

    // fused softmax over this (b,l,h)'s 16 logits; lane L holds weight[L&15]
    float lg = logits[(size_t)warp * 16 + c];
    float mx = lg;
#pragma unroll
    for (int o = 8; o; o >>= 1) mx = fmaxf(mx, __shfl_xor_sync(0xffffffffu, mx, o, 16));
    float ex = __expf(lg - mx);
    float sm = ex;
#pragma unroll
    for (int o = 8; o; o >>= 1) sm += __shfl_xor_sync(0xffffffffu, sm, o, 16);
    float wown = ex / sm;

    const float*  offp = off + (size_t)m * 256 + h * 32;
    const float*  refp = ref + (size_t)m * 8;
    const __half* vb   = value + (size_t)b * LEN_T * 256 + h * 32 + c * 2;

    float accx = 0.f, accy = 0.f;
#pragma unroll
    for (int lvl = 0; lvl < 4; lvl++) {
        const int H = cH[lvl], W = cW[lvl];
        const __half* vl = vb + (size_t)cS[lvl] * 256;
        float rx = refp[lvl * 2], ry = refp[lvl * 2 + 1];
        float bx = rx * (float)W - 0.5f;
        float by = ry * (float)H - 0.5f;
#pragma unroll
        for (int it = 0; it < 2; it++) {
            int p = it * 2 + pp;
            float x = bx + offp[(lvl * 4 + p) * 2];
            float y = by + offp[(lvl * 4 + p) * 2 + 1];
            float aw = __shfl_sync(0xffffffffu, wown, lvl * 4 + p, 16);
            float xf = floorf(x), yf = floorf(y);
            float dx = x - xf, dy = y - yf;
            int x0 = (int)xf, y0 = (int)yf;
            float w00 = (1.f - dx) * (1.f - dy) * aw;
            float w10 = dx * (1.f - dy) * aw;
            float w01 = (1.f - dx) * dy * aw;
            float w11 = dx * dy * aw;
            bool ix0 = (unsigned)x0 < (unsigned)W;
            bool ix1 = (unsigned)(x0 + 1) < (unsigned)W;
            bool iy0 = (unsigned)y0 < (unsigned)H;
            bool iy1 = (unsigned)(y0 + 1) < (unsigned)H;
            if (ix0 && iy0) {
                float2 f = __half22float2(*(const __half2*)(vl + (size_t)(y0 * W + x0) * 256));
                accx += w00 * f.x; accy += w00 * f.y;
            }
            if (ix1 && iy0) {
                float2 f = __half22float2(*(const __half2*)(vl + (size_t)(y0 * W + x0 + 1) * 256));
                accx += w10 * f.x; accy += w10 * f.y;
            }
            if (ix0 && iy1) {
                float2 f = __half22float2(*(const __half2*)(vl + (size_t)((y0 + 1) * W + x0) * 256));
                accx += w01 * f.x; accy += w01 * f.y;
            }
            if (ix1 && iy1) {
                float2 f = __half22float2(*(const __half2*)(vl + (size_t)((y0 + 1) * W + x0 + 1) * 256));
                accx += w11 * f.x; accy += w11 * f.y;
            }
        }
    }
    accx += __shfl_xor_sync(0xffffffffu, accx, 16);
    accy += __shfl_xor_sync(0xffffffffu, accy, 16);
    if (pp == 0) {
        *(__half2*)(out + (size_t)warp * 32 + c * 2) = __floats2half2_rn(accx, accy);
    }
}

// ---------------- layernorm: warp per row of 256, optional fp16 copy ----------------
__global__ void ln_warp(const float* __restrict__ x, const float* __restrict__ g,
                        const float* __restrict__ b, float* __restrict__ o,
                        __half* __restrict__ oh)
{
    int t = blockIdx.x * blockDim.x + threadIdx.x;
    int warp = t >> 5, lane = t & 31;
    if (warp >= M_TOT) return;
    const float4* row = (const float4*)(x + (size_t)warp * 256);
    float4 v0 = row[lane];
    float4 v1 = row[lane + 32];
    float s = v0.x + v0.y + v0.z + v0.w + v1.x + v1.y + v1.z + v1.w;
#pragma unroll
    for (int off = 16; off; off >>= 1) s += __shfl_xor_sync(0xffffffffu, s, off);
    float mean = s * (1.f / 256.f);
    float d[8] = {v0.x - mean, v0.y - mean, v0.z - mean, v0.w - mean,
                  v1.x - mean, v1.y - mean, v1.z - mean, v1.w - mean};
    float ss = 0.f;
#pragma unroll
    for (int i = 0; i < 8; i++) ss += d[i] * d[i];
#pragma unroll
    for (int off = 16; off; off >>= 1) ss += __shfl_xor_sync(0xffffffffu, ss, off);
    float rs = rsqrtf(ss * (1.f / 256.f) + 1e-5f);
    const float4* g4 = (const float4*)g;
    const float4* b4 = (const float4*)b;
    float4 G0 = g4[lane], G1 = g4[lane + 32];
    float4 B0 = b4[lane], B1 = b4[lane + 32];
    float4 o0 = make_float4(d[0] * rs * G0.x + B0.x, d[1] * rs * G0.y + B0.y,
                            d[2] * rs * G0.z + B0.z, d[3] * rs * G0.w + B0.w);
    float4 o1 = make_float4(d[4] * rs * G1.x + B1.x, d[5] * rs * G1.y + B1.y,
                            d[6] * rs * G1.z + B1.z, d[7] * rs * G1.w + B1.w);
    float4* orow = (float4*)(o + (size_t)warp * 256);
    orow[lane] = o0;
    orow[lane + 32] = o1;
    if (oh) {
        __half2* hrow = (__half2*)(oh + (size_t)warp * 256);
        hrow[lane * 2 + 0]  = __floats2half2_rn(o0.x, o0.y);
        hrow[lane * 2 + 1]  = __floats2half2_rn(o0.z, o0.w);
        hrow[64 + lane * 2] = __floats2half2_rn(o1.x, o1.y);
        hrow[65 + lane * 2] = __floats2half2_rn(o1.z, o1.w);
    }
}

// ---------------- launch ----------------
extern "C" void kernel_launch(void* const* d_in, const int* in_sizes, int n_in,
                              void* d_out, int out_size)
{
    const float* src   = (const float*)d_in[0];
    const float* pos   = (const float*)d_in[1];
    const float* ref   = (const float*)d_in[2];
    const float* Wv    = (const float*)d_in[3];
    const float* bv    = (const float*)d_in[4];
    const float* Woff  = (const float*)d_in[5];
    const float* boff  = (const float*)d_in[6];
    const float* Wattn = (const float*)d_in[7];
    const float* battn = (const float*)d_in[8];
    const float* Wout  = (const float*)d_in[9];
    const float* bout  = (const float*)d_in[10];
    const float* W1    = (const float*)d_in[11];
    const float* b1    = (const float*)d_in[12];
    const float* W2    = (const float*)d_in[13];
    const float* b2    = (const float*)d_in[14];
    const float* gm1   = (const float*)d_in[15];
    const float* be1   = (const float*)d_in[16];
    const float* gm2   = (const float*)d_in[17];
    const float* be2   = (const float*)d_in[18];
    float* out = (float*)d_out;

    __half *qh, *srh, *vh, *ath, *x1h, *hidh, *wth;
    float *off, *aw, *x1, *tmp;
    cudaGetSymbolAddress((void**)&qh,   g_qh);
    cudaGetSymbolAddress((void**)&srh,  g_srch);
    cudaGetSymbolAddress((void**)&vh,   g_valh);
    cudaGetSymbolAddress((void**)&off,  g_off);
    cudaGetSymbolAddress((void**)&aw,   g_aw);
    cudaGetSymbolAddress((void**)&ath,  g_ath);
    cudaGetSymbolAddress((void**)&x1,   g_x1);
    cudaGetSymbolAddress((void**)&x1h,  g_x1h);
    cudaGetSymbolAddress((void**)&hidh, g_hidh);
    cudaGetSymbolAddress((void**)&tmp,  g_tmp);
    cudaGetSymbolAddress((void**)&wth,  g_wth);

    __half* wtv    = wth + 0;
    __half* wtoff  = wth + 65536;
    __half* wtattn = wth + 131072;
    __half* wtout  = wth + 163840;
    __half* wt1    = wth + 229376;
    __half* wt2    = wth + 491520;

    const int MB = (M_TOT + 127) / 128;   // 208

    // qh = h(src+pos); srch = h(src)
    int n4 = M_TOT * D_T / 4;
    add_half<<<(n4 + 255) / 256, 256>>>(src, pos, qh, srh, n4);

    // all weight transposes in one launch
    transpose_all<<<736, dim3(32, 8)>>>(Wv, Woff, Wattn, Wout, W1, W2,
                                        wtv, wtoff, wtattn, wtout, wt1, wt2);

    // value (fp16) = srch @ Wv + bv
    hgemm<3><<<dim3(2, MB), 256>>>(srh, wtv, bv, nullptr, vh, M_TOT, 256, 256);
    // off = qh @ Woff + boff (f32)
    hgemm<0><<<dim3(2, MB), 256>>>(qh, wtoff, boff, nullptr, off, M_TOT, 256, 256);
    // attn logits = qh @ Wattn + battn (f32)
    hgemm<0><<<dim3(1, MB), 256>>>(qh, wtattn, battn, nullptr, aw, M_TOT, 128, 256);

    // sampling with fused softmax -> ath (fp16)
    {
        long threads = (long)M_TOT * NH_T * 32;
        deform_sample<<<(unsigned)((threads + 255) / 256), 256>>>(vh, off, aw, ref, ath);
    }

    // out-proj + residual -> tmp (f32)
    hgemm<2><<<dim3(2, MB), 256>>>(ath, wtout, bout, src, tmp, M_TOT, 256, 256);
    ln_warp<<<(M_TOT * 32 + 255) / 256, 256>>>(tmp, gm1, be1, x1, x1h);

    // FFN
    hgemm<1><<<dim3(8, MB), 256>>>(x1h, wt1, b1, nullptr, hidh, M_TOT, 1024, 256);
    hgemm<2><<<dim3(2, MB), 256>>>(hidh, wt2, b2, x1, tmp, M_TOT, 256, 1024);
    ln_warp<<<(M_TOT * 32 + 255) / 256, 256>>>(tmp, gm2, be2, out, nullptr);
}